// round 13
// baseline (speedup 1.0000x reference)
#include <cuda_runtime.h>
#include <cstdint>

#define BB 32
#define CL 1024
#define QL 128
#define HH 512
#define NEG (-1e30f)

// ---- scratch (device globals; no allocations allowed) ----
__device__ float g_S[(size_t)BB * CL * QL];     // raw scores
__device__ float g_Srow[(size_t)BB * CL * QL];  // row softmax
__device__ float g_T[(size_t)BB * QL * HH];     // T = Scol^T @ C (scaled)
__device__ float g_pmax[BB * 8 * QL];           // per-(b, i-tile) col max
__device__ float g_psum[BB * 8 * QL];           // per-(b, i-tile) col sum
__device__ float g_cmax[BB * QL];               // col-softmax max per j
__device__ float g_cinv[BB * QL];               // 1 / col-softmax sum per j

__device__ __forceinline__ float tf32r(float x) {
    uint32_t u;
    asm("cvt.rna.tf32.f32 %0, %1;\n" : "=r"(u) : "f"(x));
    return __uint_as_float(u);
}
__device__ __forceinline__ float4 tf4(float4 v) {
    return make_float4(tf32r(v.x), tf32r(v.y), tf32r(v.z), tf32r(v.w));
}
__device__ __forceinline__ float dot4(float4 a, float4 b) {
    return a.x * b.x + a.y * b.y + a.z * b.z + a.w * b.w;
}

__device__ __forceinline__ void mma8(float* d, const uint32_t* a, const uint32_t* b) {
    asm volatile(
        "mma.sync.aligned.m16n8k8.row.col.f32.tf32.tf32.f32 "
        "{%0,%1,%2,%3},{%4,%5,%6,%7},{%8,%9},{%0,%1,%2,%3};\n"
        : "+f"(d[0]), "+f"(d[1]), "+f"(d[2]), "+f"(d[3])
        : "r"(a[0]), "r"(a[1]), "r"(a[2]), "r"(a[3]), "r"(b[0]), "r"(b[1]));
}

// ---------------------------------------------------------------------------
// K2: S = (C*w3)@Q^T + (C@w1)[i] + (Q@w2)[j] + b.
// Fused epilogues: row-softmax (qmask) AND per-CTA column stats (cmask).
// 256 threads, tile 128(i) x 128(j), Kc=16 double-buffered, warps 4x2 (32x64).
// ---------------------------------------------------------------------------
__global__ __launch_bounds__(256) void k_sgemm(const float* __restrict__ C,
                                               const float* __restrict__ Q,
                                               const float* __restrict__ w,
                                               const float* __restrict__ bias,
                                               const int* __restrict__ qmask,
                                               const int* __restrict__ cmask) {
    __shared__ float As[2][128][20];
    __shared__ float Bs[2][128][20];
    __shared__ float scw1[128], sqw2[128];
    __shared__ int sqm[128], scm[128];
    __shared__ float pm[128][2], ps[128][2];
    __shared__ float cpm[4][128], cps[4][128];

    int b = blockIdx.z, i0 = blockIdx.x * 128;
    int t = threadIdx.x, lane = t & 31, wid = t >> 5;
    int m0w = (wid & 3) * 32, n0w = (wid >> 2) * 64;
    int r = lane >> 2, c = lane & 3;
    const float* w1 = w;
    const float* w2 = w + HH;
    const float* w3 = w + 2 * HH;
    const float* Cb = C + ((size_t)b * CL + i0) * HH;
    const float* Qb = Q + (size_t)b * QL * HH;
    int lr = t >> 1, lk = (t & 1) * 8;

    if (t < 128) {
        sqm[t] = qmask[b * QL + t];
        scm[t] = cmask[b * CL + i0 + t];
    }

    float cwacc = 0.f, qwacc = 0.f;
    float4 a1, a2, q1, q2, w3a, w3b;
    a1 = *(const float4*)(Cb + (size_t)lr * HH + lk);
    a2 = *(const float4*)(Cb + (size_t)lr * HH + lk + 4);
    q1 = *(const float4*)(Qb + (size_t)lr * HH + lk);
    q2 = *(const float4*)(Qb + (size_t)lr * HH + lk + 4);
    w3a = *(const float4*)(w3 + lk);
    w3b = *(const float4*)(w3 + lk + 4);
    cwacc += dot4(a1, *(const float4*)(w1 + lk)) + dot4(a2, *(const float4*)(w1 + lk + 4));
    qwacc += dot4(q1, *(const float4*)(w2 + lk)) + dot4(q2, *(const float4*)(w2 + lk + 4));
    *(float4*)&As[0][lr][lk] = make_float4(tf32r(a1.x * w3a.x), tf32r(a1.y * w3a.y),
                                           tf32r(a1.z * w3a.z), tf32r(a1.w * w3a.w));
    *(float4*)&As[0][lr][lk + 4] = make_float4(tf32r(a2.x * w3b.x), tf32r(a2.y * w3b.y),
                                               tf32r(a2.z * w3b.z), tf32r(a2.w * w3b.w));
    *(float4*)&Bs[0][lr][lk] = tf4(q1);
    *(float4*)&Bs[0][lr][lk + 4] = tf4(q2);
    __syncthreads();

    float acc[2][8][4] = {};
    for (int kk = 0; kk < HH; kk += 16) {
        int cur = (kk >> 4) & 1;
        bool more = (kk + 16) < HH;
        if (more) {
            int k2 = kk + 16;
            a1 = *(const float4*)(Cb + (size_t)lr * HH + k2 + lk);
            a2 = *(const float4*)(Cb + (size_t)lr * HH + k2 + lk + 4);
            q1 = *(const float4*)(Qb + (size_t)lr * HH + k2 + lk);
            q2 = *(const float4*)(Qb + (size_t)lr * HH + k2 + lk + 4);
            w3a = *(const float4*)(w3 + k2 + lk);
            w3b = *(const float4*)(w3 + k2 + lk + 4);
            cwacc += dot4(a1, *(const float4*)(w1 + k2 + lk)) +
                     dot4(a2, *(const float4*)(w1 + k2 + lk + 4));
            qwacc += dot4(q1, *(const float4*)(w2 + k2 + lk)) +
                     dot4(q2, *(const float4*)(w2 + k2 + lk + 4));
        }
#pragma unroll
        for (int h = 0; h < 2; h++) {
            int ck = h * 8 + c;
            uint32_t af[2][4], bf[8][2];
#pragma unroll
            for (int mi = 0; mi < 2; mi++) {
                int mb = m0w + mi * 16;
                af[mi][0] = __float_as_uint(As[cur][mb + r][ck]);
                af[mi][1] = __float_as_uint(As[cur][mb + r + 8][ck]);
                af[mi][2] = __float_as_uint(As[cur][mb + r][ck + 4]);
                af[mi][3] = __float_as_uint(As[cur][mb + r + 8][ck + 4]);
            }
#pragma unroll
            for (int ni = 0; ni < 8; ni++) {
                int nb = n0w + ni * 8 + r;
                bf[ni][0] = __float_as_uint(Bs[cur][nb][ck]);
                bf[ni][1] = __float_as_uint(Bs[cur][nb][ck + 4]);
            }
#pragma unroll
            for (int mi = 0; mi < 2; mi++)
#pragma unroll
                for (int ni = 0; ni < 8; ni++) mma8(acc[mi][ni], af[mi], bf[ni]);
        }
        if (more) {
            int nxt = cur ^ 1;
            *(float4*)&As[nxt][lr][lk] = make_float4(tf32r(a1.x * w3a.x), tf32r(a1.y * w3a.y),
                                                     tf32r(a1.z * w3a.z), tf32r(a1.w * w3a.w));
            *(float4*)&As[nxt][lr][lk + 4] = make_float4(tf32r(a2.x * w3b.x), tf32r(a2.y * w3b.y),
                                                         tf32r(a2.z * w3b.z), tf32r(a2.w * w3b.w));
            *(float4*)&Bs[nxt][lr][lk] = tf4(q1);
            *(float4*)&Bs[nxt][lr][lk + 4] = tf4(q2);
        }
        __syncthreads();
    }

    cwacc += __shfl_xor_sync(0xffffffffu, cwacc, 1);
    qwacc += __shfl_xor_sync(0xffffffffu, qwacc, 1);
    if ((t & 1) == 0) { scw1[lr] = cwacc; sqw2[lr] = qwacc; }
    __syncthreads();

    float b0 = bias[0];
    int nhalf = wid >> 2;
    float qw[8][2];
#pragma unroll
    for (int ni = 0; ni < 8; ni++) {
        int j = n0w + ni * 8 + (c << 1);
        qw[ni][0] = sqw2[j];
        qw[ni][1] = sqw2[j + 1];
    }
#pragma unroll
    for (int mi = 0; mi < 2; mi++)
#pragma unroll
        for (int dh = 0; dh < 2; dh++) {
            float cw = scw1[m0w + mi * 16 + r + dh * 8] + b0;
#pragma unroll
            for (int ni = 0; ni < 8; ni++) {
                acc[mi][ni][dh * 2 + 0] += cw + qw[ni][0];
                acc[mi][ni][dh * 2 + 1] += cw + qw[ni][1];
            }
        }
    // ---- row softmax (qmask) ----
#pragma unroll
    for (int mi = 0; mi < 2; mi++)
#pragma unroll
        for (int dh = 0; dh < 2; dh++) {
            int il = m0w + mi * 16 + r + dh * 8;
            float mx = NEG;
#pragma unroll
            for (int ni = 0; ni < 8; ni++) {
                int j = n0w + ni * 8 + (c << 1);
                mx = fmaxf(mx, sqm[j] ? acc[mi][ni][dh * 2] : NEG);
                mx = fmaxf(mx, sqm[j + 1] ? acc[mi][ni][dh * 2 + 1] : NEG);
            }
            mx = fmaxf(mx, __shfl_xor_sync(0xffffffffu, mx, 1));
            mx = fmaxf(mx, __shfl_xor_sync(0xffffffffu, mx, 2));
            if (c == 0) pm[il][nhalf] = mx;
        }
    __syncthreads();
    float m2[2][2];
#pragma unroll
    for (int mi = 0; mi < 2; mi++)
#pragma unroll
        for (int dh = 0; dh < 2; dh++) {
            int il = m0w + mi * 16 + r + dh * 8;
            float m = fmaxf(pm[il][0], pm[il][1]);
            m2[mi][dh] = m;
            float sum = 0.f;
#pragma unroll
            for (int ni = 0; ni < 8; ni++) {
                int j = n0w + ni * 8 + (c << 1);
                float x0 = sqm[j] ? acc[mi][ni][dh * 2] : NEG;
                float x1 = sqm[j + 1] ? acc[mi][ni][dh * 2 + 1] : NEG;
                sum += __expf(x0 - m) + __expf(x1 - m);
            }
            sum += __shfl_xor_sync(0xffffffffu, sum, 1);
            sum += __shfl_xor_sync(0xffffffffu, sum, 2);
            if (c == 0) ps[il][nhalf] = sum;
        }
    __syncthreads();
#pragma unroll
    for (int mi = 0; mi < 2; mi++)
#pragma unroll
        for (int dh = 0; dh < 2; dh++) {
            int il = m0w + mi * 16 + r + dh * 8;
            int i = i0 + il;
            float m = m2[mi][dh];
            float inv = 1.f / (ps[il][0] + ps[il][1]);
            float* So = g_S + ((size_t)b * CL + i) * QL;
            float* Sr = g_Srow + ((size_t)b * CL + i) * QL;
#pragma unroll
            for (int ni = 0; ni < 8; ni++) {
                int j = n0w + ni * 8 + (c << 1);
                float v0 = acc[mi][ni][dh * 2], v1 = acc[mi][ni][dh * 2 + 1];
                *(float2*)(So + j) = make_float2(v0, v1);
                float e0 = __expf((sqm[j] ? v0 : NEG) - m) * inv;
                float e1 = __expf((sqm[j + 1] ? v1 : NEG) - m) * inv;
                *(float2*)(Sr + j) = make_float2(e0, e1);
            }
        }

    // ---- column-softmax partial stats (cmask over rows), per CTA tile ----
    int mw = wid & 3;
    {
        float cmx[8][2];
#pragma unroll
        for (int ni = 0; ni < 8; ni++) { cmx[ni][0] = NEG; cmx[ni][1] = NEG; }
#pragma unroll
        for (int mi = 0; mi < 2; mi++)
#pragma unroll
            for (int dh = 0; dh < 2; dh++) {
                int il = m0w + mi * 16 + r + dh * 8;
                bool ck = scm[il] != 0;
#pragma unroll
                for (int ni = 0; ni < 8; ni++) {
                    cmx[ni][0] = fmaxf(cmx[ni][0], ck ? acc[mi][ni][dh * 2] : NEG);
                    cmx[ni][1] = fmaxf(cmx[ni][1], ck ? acc[mi][ni][dh * 2 + 1] : NEG);
                }
            }
#pragma unroll
        for (int ni = 0; ni < 8; ni++)
#pragma unroll
            for (int jj = 0; jj < 2; jj++) {
                float v = cmx[ni][jj];
                v = fmaxf(v, __shfl_xor_sync(0xffffffffu, v, 4));
                v = fmaxf(v, __shfl_xor_sync(0xffffffffu, v, 8));
                v = fmaxf(v, __shfl_xor_sync(0xffffffffu, v, 16));
                cmx[ni][jj] = v;
            }
        if (r == 0) {
#pragma unroll
            for (int ni = 0; ni < 8; ni++) {
                int j = n0w + ni * 8 + (c << 1);
                cpm[mw][j] = cmx[ni][0];
                cpm[mw][j + 1] = cmx[ni][1];
            }
        }
    }
    __syncthreads();
    {
        float csm[8][2];
#pragma unroll
        for (int ni = 0; ni < 8; ni++) { csm[ni][0] = 0.f; csm[ni][1] = 0.f; }
        float Mj[8][2];
#pragma unroll
        for (int ni = 0; ni < 8; ni++)
#pragma unroll
            for (int jj = 0; jj < 2; jj++) {
                int j = n0w + ni * 8 + (c << 1) + jj;
                Mj[ni][jj] = fmaxf(fmaxf(cpm[0][j], cpm[1][j]), fmaxf(cpm[2][j], cpm[3][j]));
            }
#pragma unroll
        for (int mi = 0; mi < 2; mi++)
#pragma unroll
            for (int dh = 0; dh < 2; dh++) {
                int il = m0w + mi * 16 + r + dh * 8;
                bool ck = scm[il] != 0;
#pragma unroll
                for (int ni = 0; ni < 8; ni++) {
                    csm[ni][0] += ck ? __expf(acc[mi][ni][dh * 2] - Mj[ni][0]) : 0.f;
                    csm[ni][1] += ck ? __expf(acc[mi][ni][dh * 2 + 1] - Mj[ni][1]) : 0.f;
                }
            }
#pragma unroll
        for (int ni = 0; ni < 8; ni++)
#pragma unroll
            for (int jj = 0; jj < 2; jj++) {
                float v = csm[ni][jj];
                v += __shfl_xor_sync(0xffffffffu, v, 4);
                v += __shfl_xor_sync(0xffffffffu, v, 8);
                v += __shfl_xor_sync(0xffffffffu, v, 16);
                csm[ni][jj] = v;
            }
        if (r == 0) {
#pragma unroll
            for (int ni = 0; ni < 8; ni++) {
                int j = n0w + ni * 8 + (c << 1);
                cps[mw][j] = csm[ni][0];
                cps[mw][j + 1] = csm[ni][1];
            }
        }
    }
    __syncthreads();
    if (t < 128) {
        float M = fmaxf(fmaxf(cpm[0][t], cpm[1][t]), fmaxf(cpm[2][t], cpm[3][t]));
        float S_ = cps[0][t] + cps[1][t] + cps[2][t] + cps[3][t];
        int idx = (b * 8 + blockIdx.x) * QL + t;
        g_pmax[idx] = M;
        g_psum[idx] = S_;
    }
}

// ---------------------------------------------------------------------------
// K4': combine per-tile column partials -> g_cmax, g_cinv. Tiny.
// ---------------------------------------------------------------------------
__global__ void k_colcomb() {
    int b = blockIdx.x, j = threadIdx.x;
    float M = NEG;
#pragma unroll
    for (int tl = 0; tl < 8; tl++) M = fmaxf(M, g_pmax[(b * 8 + tl) * QL + j]);
    float S_ = 0.f;
#pragma unroll
    for (int tl = 0; tl < 8; tl++) {
        int idx = (b * 8 + tl) * QL + j;
        S_ += g_psum[idx] * __expf(g_pmax[idx] - M);
    }
    g_cmax[b * QL + j] = M;
    g_cinv[b * QL + j] = 1.f / S_;
}

// ---------------------------------------------------------------------------
// K5: T[j,h] = (1/s[j]) * sum_i [cm[i] ? exp(S[i,j]-m[j]) : 0] * C[i,h]
// 256 threads, 8 warps 4(m=j) x 2(n=h), warp 32x64, tile 128x128, Kc=16.
// ---------------------------------------------------------------------------
__global__ __launch_bounds__(256) void k_tgemm(const float* __restrict__ C,
                                               const int* __restrict__ cmask) {
    __shared__ float Ss[2][16][136];
    __shared__ float Cs[2][16][136];
    __shared__ float smax[128], sinv[128];
    int b = blockIdx.z, h0 = blockIdx.y * 128;
    int t = threadIdx.x, lane = t & 31, wid = t >> 5;
    int m0w = (wid & 3) * 32, n0w = (wid >> 2) * 64;
    int r = lane >> 2, c = lane & 3;
    const float* Sb = g_S + (size_t)b * CL * QL;
    const float* Cb = C + (size_t)b * CL * HH;
    const int* cm = cmask + b * CL;
    int si = t >> 5, sj = (t & 31) * 4;
    int ci = t >> 4, ch = (t & 15) * 8;

    if (t < 128) {
        smax[t] = g_cmax[b * QL + t];
        sinv[t] = g_cinv[b * QL + t];
    }
    __syncthreads();
    float4 msj = *(const float4*)(smax + sj);

    float4 s1, s2, c1, c2;
    int cm0, cm1;
    s1 = *(const float4*)(Sb + (size_t)si * QL + sj);
    s2 = *(const float4*)(Sb + (size_t)(si + 8) * QL + sj);
    c1 = *(const float4*)(Cb + (size_t)ci * HH + h0 + ch);
    c2 = *(const float4*)(Cb + (size_t)ci * HH + h0 + ch + 4);
    cm0 = cm[si];
    cm1 = cm[si + 8];
    {
        float4 e1 = cm0 ? make_float4(__expf(s1.x - msj.x), __expf(s1.y - msj.y),
                                      __expf(s1.z - msj.z), __expf(s1.w - msj.w))
                        : make_float4(0.f, 0.f, 0.f, 0.f);
        float4 e2 = cm1 ? make_float4(__expf(s2.x - msj.x), __expf(s2.y - msj.y),
                                      __expf(s2.z - msj.z), __expf(s2.w - msj.w))
                        : make_float4(0.f, 0.f, 0.f, 0.f);
        *(float4*)&Ss[0][si][sj] = tf4(e1);
        *(float4*)&Ss[0][si + 8][sj] = tf4(e2);
        *(float4*)&Cs[0][ci][ch] = tf4(c1);
        *(float4*)&Cs[0][ci][ch + 4] = tf4(c2);
    }
    __syncthreads();

    float acc[2][8][4] = {};
    for (int kk = 0; kk < CL; kk += 16) {
        int cur = (kk >> 4) & 1;
        bool more = (kk + 16) < CL;
        if (more) {
            int k2 = kk + 16;
            s1 = *(const float4*)(Sb + (size_t)(k2 + si) * QL + sj);
            s2 = *(const float4*)(Sb + (size_t)(k2 + si + 8) * QL + sj);
            c1 = *(const float4*)(Cb + (size_t)(k2 + ci) * HH + h0 + ch);
            c2 = *(const float4*)(Cb + (size_t)(k2 + ci) * HH + h0 + ch + 4);
            cm0 = cm[k2 + si];
            cm1 = cm[k2 + si + 8];
        }
#pragma unroll
        for (int h = 0; h < 2; h++) {
            int ck = h * 8 + c;
            uint32_t af[2][4], bf[8][2];
#pragma unroll
            for (int mi = 0; mi < 2; mi++) {
                int mb = m0w + mi * 16;
                af[mi][0] = __float_as_uint(Ss[cur][ck][mb + r]);
                af[mi][1] = __float_as_uint(Ss[cur][ck][mb + r + 8]);
                af[mi][2] = __float_as_uint(Ss[cur][ck + 4][mb + r]);
                af[mi][3] = __float_as_uint(Ss[cur][ck + 4][mb + r + 8]);
            }
#pragma unroll
            for (int ni = 0; ni < 8; ni++) {
                int nb = n0w + ni * 8 + r;
                bf[ni][0] = __float_as_uint(Cs[cur][ck][nb]);
                bf[ni][1] = __float_as_uint(Cs[cur][ck + 4][nb]);
            }
#pragma unroll
            for (int mi = 0; mi < 2; mi++)
#pragma unroll
                for (int ni = 0; ni < 8; ni++) mma8(acc[mi][ni], af[mi], bf[ni]);
        }
        if (more) {
            int nxt = cur ^ 1;
            float4 e1 = cm0 ? make_float4(__expf(s1.x - msj.x), __expf(s1.y - msj.y),
                                          __expf(s1.z - msj.z), __expf(s1.w - msj.w))
                            : make_float4(0.f, 0.f, 0.f, 0.f);
            float4 e2 = cm1 ? make_float4(__expf(s2.x - msj.x), __expf(s2.y - msj.y),
                                          __expf(s2.z - msj.z), __expf(s2.w - msj.w))
                            : make_float4(0.f, 0.f, 0.f, 0.f);
            *(float4*)&Ss[nxt][si][sj] = tf4(e1);
            *(float4*)&Ss[nxt][si + 8][sj] = tf4(e2);
            *(float4*)&Cs[nxt][ci][ch] = tf4(c1);
            *(float4*)&Cs[nxt][ci][ch + 4] = tf4(c2);
        }
        __syncthreads();
    }
#pragma unroll
    for (int mi = 0; mi < 2; mi++)
#pragma unroll
        for (int dh = 0; dh < 2; dh++) {
            int jl = m0w + mi * 16 + r + dh * 8;
            float inv = sinv[jl];
            float* To = g_T + ((size_t)b * QL + jl) * HH + h0;
#pragma unroll
            for (int ni = 0; ni < 8; ni++) {
                int h = n0w + ni * 8 + (c << 1);
                *(float2*)(To + h) = make_float2(acc[mi][ni][dh * 2] * inv,
                                                 acc[mi][ni][dh * 2 + 1] * inv);
            }
        }
}

// ---------------------------------------------------------------------------
// K6: fused A = Srow@Q and Bm = Srow@T (K=128), writes concat output.
// 512 threads, 16 warps 4(m) x 4(n), warp tile 64x32, CTA tile 256(i) x 128(h).
// A fragments feed BOTH MMAs -> LDS/MMA ratio 1.0. dyn smem 75776 B.
// ---------------------------------------------------------------------------
#define K6_AS(bu, i, k) dsm[(bu) * 5120 + (i) * 20 + (k)]
#define K6_QS(bu, k, n) dsm[10240 + (bu) * 2176 + (k) * 136 + (n)]
#define K6_TS(bu, k, n) dsm[14592 + (bu) * 2176 + (k) * 136 + (n)]

__global__ __launch_bounds__(512) void k_out(const float* __restrict__ C,
                                             const float* __restrict__ Q,
                                             float* __restrict__ out) {
    extern __shared__ float dsm[];
    int b = blockIdx.z, i0 = blockIdx.x * 256, h0 = blockIdx.y * 128;
    int t = threadIdx.x, lane = t & 31, wid = t >> 5;
    int m0w = (wid & 3) * 64, n0w = (wid >> 2) * 32;
    int r = lane >> 2, c = lane & 3;
    const float* Sr = g_Srow + ((size_t)b * CL + i0) * QL;
    const float* Qb = Q + (size_t)b * QL * HH;
    const float* Tb = g_T + (size_t)b * QL * HH;
    int ar = t >> 1, ak = (t & 1) * 8;   // A fill: 256 rows, 2 float4 each
    int kr = t >> 5, nc = (t & 31) * 4;  // B fill: 16 rows, 1 float4 each of Q,T

    float4 av1, av2, qv, tv;
    av1 = *(const float4*)(Sr + (size_t)ar * QL + ak);
    av2 = *(const float4*)(Sr + (size_t)ar * QL + ak + 4);
    qv = *(const float4*)(Qb + (size_t)kr * HH + h0 + nc);
    tv = *(const float4*)(Tb + (size_t)kr * HH + h0 + nc);
    *(float4*)&K6_AS(0, ar, ak) = tf4(av1);
    *(float4*)&K6_AS(0, ar, ak + 4) = tf4(av2);
    *(float4*)&K6_QS(0, kr, nc) = tf4(qv);
    *(float4*)&K6_TS(0, kr, nc) = tf4(tv);
    __syncthreads();

    float accA[4][4][4] = {}, accB[4][4][4] = {};
    for (int kk = 0; kk < QL; kk += 16) {
        int cur = (kk >> 4) & 1;
        bool more = (kk + 16) < QL;
        if (more) {
            int k2 = kk + 16;
            av1 = *(const float4*)(Sr + (size_t)ar * QL + k2 + ak);
            av2 = *(const float4*)(Sr + (size_t)ar * QL + k2 + ak + 4);
            qv = *(const float4*)(Qb + (size_t)(k2 + kr) * HH + h0 + nc);
            tv = *(const float4*)(Tb + (size_t)(k2 + kr) * HH + h0 + nc);
        }
#pragma unroll
        for (int h = 0; h < 2; h++) {
            int ck = h * 8 + c;
            uint32_t af[4][4], bq[4][2], bt[4][2];
#pragma unroll
            for (int mi = 0; mi < 4; mi++) {
                int mb = m0w + mi * 16;
                af[mi][0] = __float_as_uint(K6_AS(cur, mb + r, ck));
                af[mi][1] = __float_as_uint(K6_AS(cur, mb + r + 8, ck));
                af[mi][2] = __float_as_uint(K6_AS(cur, mb + r, ck + 4));
                af[mi][3] = __float_as_uint(K6_AS(cur, mb + r + 8, ck + 4));
            }
#pragma unroll
            for (int ni = 0; ni < 4; ni++) {
                int nb = n0w + ni * 8 + r;
                bq[ni][0] = __float_as_uint(K6_QS(cur, ck, nb));
                bq[ni][1] = __float_as_uint(K6_QS(cur, ck + 4, nb));
                bt[ni][0] = __float_as_uint(K6_TS(cur, ck, nb));
                bt[ni][1] = __float_as_uint(K6_TS(cur, ck + 4, nb));
            }
#pragma unroll
            for (int mi = 0; mi < 4; mi++)
#pragma unroll
                for (int ni = 0; ni < 4; ni++) {
                    mma8(accA[mi][ni], af[mi], bq[ni]);
                    mma8(accB[mi][ni], af[mi], bt[ni]);
                }
        }
        if (more) {
            int nxt = cur ^ 1;
            *(float4*)&K6_AS(nxt, ar, ak) = tf4(av1);
            *(float4*)&K6_AS(nxt, ar, ak + 4) = tf4(av2);
            *(float4*)&K6_QS(nxt, kr, nc) = tf4(qv);
            *(float4*)&K6_TS(nxt, kr, nc) = tf4(tv);
        }
        __syncthreads();
    }
    const float* Cb = C + (size_t)b * CL * HH;
#pragma unroll
    for (int mi = 0; mi < 4; mi++)
#pragma unroll
        for (int dh = 0; dh < 2; dh++) {
            int i = i0 + m0w + mi * 16 + r + dh * 8;
            const float* Crow = Cb + (size_t)i * HH;
            float* ob = out + ((size_t)b * CL + i) * (4 * HH);
#pragma unroll
            for (int ni = 0; ni < 4; ni++) {
                int h = h0 + n0w + ni * 8 + (c << 1);
                float2 cv = *(const float2*)(Crow + h);
                float2 a2 = make_float2(accA[mi][ni][dh * 2], accA[mi][ni][dh * 2 + 1]);
                float2 b2 = make_float2(accB[mi][ni][dh * 2], accB[mi][ni][dh * 2 + 1]);
                *(float2*)(ob + h) = cv;
                *(float2*)(ob + HH + h) = a2;
                *(float2*)(ob + 2 * HH + h) = make_float2(cv.x * a2.x, cv.y * a2.y);
                *(float2*)(ob + 3 * HH + h) = make_float2(cv.x * b2.x, cv.y * b2.y);
            }
        }
}

// ---------------------------------------------------------------------------
extern "C" void kernel_launch(void* const* d_in, const int* in_sizes, int n_in,
                              void* d_out, int out_size) {
    const float* C = (const float*)d_in[0];
    const float* Q = (const float*)d_in[1];
    const int* cmask = (const int*)d_in[2];
    const int* qmask = (const int*)d_in[3];
    const float* w = (const float*)d_in[4];
    const float* bias = (const float*)d_in[5];
    float* out = (float*)d_out;

    static bool attr_done = false;
    if (!attr_done) {
        cudaFuncSetAttribute(k_out, cudaFuncAttributeMaxDynamicSharedMemorySize, 75776);
        attr_done = true;
    }

    k_sgemm<<<dim3(8, 1, BB), 256>>>(C, Q, w, bias, qmask, cmask);
    k_colcomb<<<BB, 128>>>();
    k_tgemm<<<dim3(1, 4, BB), 256>>>(C, cmask);
    k_out<<<dim3(4, 4, BB), 512, 75776>>>(C, Q, out);
}

// round 15
// speedup vs baseline: 1.2262x; 1.2262x over previous
#include <cuda_runtime.h>
#include <cstdint>

#define BB 32
#define CL 1024
#define QL 128
#define HH 512
#define NEG (-1e30f)

// ---- scratch (device globals; no allocations allowed) ----
__device__ float g_S[(size_t)BB * CL * QL];     // raw scores
__device__ float g_Srow[(size_t)BB * CL * QL];  // row softmax
__device__ float g_T[(size_t)BB * QL * HH];     // T = Scol^T @ C (scaled)
__device__ float g_pmax[BB * 8 * QL];           // per-(b, i-tile) col max
__device__ float g_psum[BB * 8 * QL];           // per-(b, i-tile) col sum
__device__ float g_cmax[BB * QL];               // col-softmax max per j
__device__ float g_cinv[BB * QL];               // 1 / col-softmax sum per j

__device__ __forceinline__ float tf32r(float x) {
    uint32_t u;
    asm("cvt.rna.tf32.f32 %0, %1;\n" : "=r"(u) : "f"(x));
    return __uint_as_float(u);
}
__device__ __forceinline__ float4 tf4(float4 v) {
    return make_float4(tf32r(v.x), tf32r(v.y), tf32r(v.z), tf32r(v.w));
}
__device__ __forceinline__ float dot4(float4 a, float4 b) {
    return a.x * b.x + a.y * b.y + a.z * b.z + a.w * b.w;
}

__device__ __forceinline__ void mma8(float* d, const uint32_t* a, const uint32_t* b) {
    asm volatile(
        "mma.sync.aligned.m16n8k8.row.col.f32.tf32.tf32.f32 "
        "{%0,%1,%2,%3},{%4,%5,%6,%7},{%8,%9},{%0,%1,%2,%3};\n"
        : "+f"(d[0]), "+f"(d[1]), "+f"(d[2]), "+f"(d[3])
        : "r"(a[0]), "r"(a[1]), "r"(a[2]), "r"(a[3]), "r"(b[0]), "r"(b[1]));
}

// ---------------------------------------------------------------------------
// K2: S = (C*w3)@Q^T + (C@w1)[i] + (Q@w2)[j] + b.
// Fused epilogues: row-softmax (qmask) AND per-CTA column stats (cmask).
// 256 threads, tile 128(i) x 128(j), Kc=16 double-buffered, warps 4x2 (32x64).
// ---------------------------------------------------------------------------
__global__ __launch_bounds__(256) void k_sgemm(const float* __restrict__ C,
                                               const float* __restrict__ Q,
                                               const float* __restrict__ w,
                                               const float* __restrict__ bias,
                                               const int* __restrict__ qmask,
                                               const int* __restrict__ cmask) {
    __shared__ float As[2][128][20];
    __shared__ float Bs[2][128][20];
    __shared__ float scw1[128], sqw2[128];
    __shared__ int sqm[128], scm[128];
    __shared__ float pm[128][2], ps[128][2];
    __shared__ float cpm[4][128], cps[4][128];

    int b = blockIdx.z, i0 = blockIdx.x * 128;
    int t = threadIdx.x, lane = t & 31, wid = t >> 5;
    int m0w = (wid & 3) * 32, n0w = (wid >> 2) * 64;
    int r = lane >> 2, c = lane & 3;
    const float* w1 = w;
    const float* w2 = w + HH;
    const float* w3 = w + 2 * HH;
    const float* Cb = C + ((size_t)b * CL + i0) * HH;
    const float* Qb = Q + (size_t)b * QL * HH;
    int lr = t >> 1, lk = (t & 1) * 8;

    if (t < 128) {
        sqm[t] = qmask[b * QL + t];
        scm[t] = cmask[b * CL + i0 + t];
    }

    float cwacc = 0.f, qwacc = 0.f;
    float4 a1, a2, q1, q2, w3a, w3b;
    a1 = *(const float4*)(Cb + (size_t)lr * HH + lk);
    a2 = *(const float4*)(Cb + (size_t)lr * HH + lk + 4);
    q1 = *(const float4*)(Qb + (size_t)lr * HH + lk);
    q2 = *(const float4*)(Qb + (size_t)lr * HH + lk + 4);
    w3a = *(const float4*)(w3 + lk);
    w3b = *(const float4*)(w3 + lk + 4);
    cwacc += dot4(a1, *(const float4*)(w1 + lk)) + dot4(a2, *(const float4*)(w1 + lk + 4));
    qwacc += dot4(q1, *(const float4*)(w2 + lk)) + dot4(q2, *(const float4*)(w2 + lk + 4));
    *(float4*)&As[0][lr][lk] = make_float4(tf32r(a1.x * w3a.x), tf32r(a1.y * w3a.y),
                                           tf32r(a1.z * w3a.z), tf32r(a1.w * w3a.w));
    *(float4*)&As[0][lr][lk + 4] = make_float4(tf32r(a2.x * w3b.x), tf32r(a2.y * w3b.y),
                                               tf32r(a2.z * w3b.z), tf32r(a2.w * w3b.w));
    *(float4*)&Bs[0][lr][lk] = tf4(q1);
    *(float4*)&Bs[0][lr][lk + 4] = tf4(q2);
    __syncthreads();

    float acc[2][8][4] = {};
    for (int kk = 0; kk < HH; kk += 16) {
        int cur = (kk >> 4) & 1;
        bool more = (kk + 16) < HH;
        if (more) {
            int k2 = kk + 16;
            a1 = *(const float4*)(Cb + (size_t)lr * HH + k2 + lk);
            a2 = *(const float4*)(Cb + (size_t)lr * HH + k2 + lk + 4);
            q1 = *(const float4*)(Qb + (size_t)lr * HH + k2 + lk);
            q2 = *(const float4*)(Qb + (size_t)lr * HH + k2 + lk + 4);
            w3a = *(const float4*)(w3 + k2 + lk);
            w3b = *(const float4*)(w3 + k2 + lk + 4);
            cwacc += dot4(a1, *(const float4*)(w1 + k2 + lk)) +
                     dot4(a2, *(const float4*)(w1 + k2 + lk + 4));
            qwacc += dot4(q1, *(const float4*)(w2 + k2 + lk)) +
                     dot4(q2, *(const float4*)(w2 + k2 + lk + 4));
        }
#pragma unroll
        for (int h = 0; h < 2; h++) {
            int ck = h * 8 + c;
            uint32_t af[2][4], bf[8][2];
#pragma unroll
            for (int mi = 0; mi < 2; mi++) {
                int mb = m0w + mi * 16;
                af[mi][0] = __float_as_uint(As[cur][mb + r][ck]);
                af[mi][1] = __float_as_uint(As[cur][mb + r + 8][ck]);
                af[mi][2] = __float_as_uint(As[cur][mb + r][ck + 4]);
                af[mi][3] = __float_as_uint(As[cur][mb + r + 8][ck + 4]);
            }
#pragma unroll
            for (int ni = 0; ni < 8; ni++) {
                int nb = n0w + ni * 8 + r;
                bf[ni][0] = __float_as_uint(Bs[cur][nb][ck]);
                bf[ni][1] = __float_as_uint(Bs[cur][nb][ck + 4]);
            }
#pragma unroll
            for (int mi = 0; mi < 2; mi++)
#pragma unroll
                for (int ni = 0; ni < 8; ni++) mma8(acc[mi][ni], af[mi], bf[ni]);
        }
        if (more) {
            int nxt = cur ^ 1;
            *(float4*)&As[nxt][lr][lk] = make_float4(tf32r(a1.x * w3a.x), tf32r(a1.y * w3a.y),
                                                     tf32r(a1.z * w3a.z), tf32r(a1.w * w3a.w));
            *(float4*)&As[nxt][lr][lk + 4] = make_float4(tf32r(a2.x * w3b.x), tf32r(a2.y * w3b.y),
                                                         tf32r(a2.z * w3b.z), tf32r(a2.w * w3b.w));
            *(float4*)&Bs[nxt][lr][lk] = tf4(q1);
            *(float4*)&Bs[nxt][lr][lk + 4] = tf4(q2);
        }
        __syncthreads();
    }

    cwacc += __shfl_xor_sync(0xffffffffu, cwacc, 1);
    qwacc += __shfl_xor_sync(0xffffffffu, qwacc, 1);
    if ((t & 1) == 0) { scw1[lr] = cwacc; sqw2[lr] = qwacc; }
    __syncthreads();

    float b0 = bias[0];
    int nhalf = wid >> 2;
    float qw[8][2];
#pragma unroll
    for (int ni = 0; ni < 8; ni++) {
        int j = n0w + ni * 8 + (c << 1);
        qw[ni][0] = sqw2[j];
        qw[ni][1] = sqw2[j + 1];
    }
#pragma unroll
    for (int mi = 0; mi < 2; mi++)
#pragma unroll
        for (int dh = 0; dh < 2; dh++) {
            float cw = scw1[m0w + mi * 16 + r + dh * 8] + b0;
#pragma unroll
            for (int ni = 0; ni < 8; ni++) {
                acc[mi][ni][dh * 2 + 0] += cw + qw[ni][0];
                acc[mi][ni][dh * 2 + 1] += cw + qw[ni][1];
            }
        }
    // ---- row softmax (qmask) ----
#pragma unroll
    for (int mi = 0; mi < 2; mi++)
#pragma unroll
        for (int dh = 0; dh < 2; dh++) {
            int il = m0w + mi * 16 + r + dh * 8;
            float mx = NEG;
#pragma unroll
            for (int ni = 0; ni < 8; ni++) {
                int j = n0w + ni * 8 + (c << 1);
                mx = fmaxf(mx, sqm[j] ? acc[mi][ni][dh * 2] : NEG);
                mx = fmaxf(mx, sqm[j + 1] ? acc[mi][ni][dh * 2 + 1] : NEG);
            }
            mx = fmaxf(mx, __shfl_xor_sync(0xffffffffu, mx, 1));
            mx = fmaxf(mx, __shfl_xor_sync(0xffffffffu, mx, 2));
            if (c == 0) pm[il][nhalf] = mx;
        }
    __syncthreads();
    float m2[2][2];
#pragma unroll
    for (int mi = 0; mi < 2; mi++)
#pragma unroll
        for (int dh = 0; dh < 2; dh++) {
            int il = m0w + mi * 16 + r + dh * 8;
            float m = fmaxf(pm[il][0], pm[il][1]);
            m2[mi][dh] = m;
            float sum = 0.f;
#pragma unroll
            for (int ni = 0; ni < 8; ni++) {
                int j = n0w + ni * 8 + (c << 1);
                float x0 = sqm[j] ? acc[mi][ni][dh * 2] : NEG;
                float x1 = sqm[j + 1] ? acc[mi][ni][dh * 2 + 1] : NEG;
                sum += __expf(x0 - m) + __expf(x1 - m);
            }
            sum += __shfl_xor_sync(0xffffffffu, sum, 1);
            sum += __shfl_xor_sync(0xffffffffu, sum, 2);
            if (c == 0) ps[il][nhalf] = sum;
        }
    __syncthreads();
#pragma unroll
    for (int mi = 0; mi < 2; mi++)
#pragma unroll
        for (int dh = 0; dh < 2; dh++) {
            int il = m0w + mi * 16 + r + dh * 8;
            int i = i0 + il;
            float m = m2[mi][dh];
            float inv = 1.f / (ps[il][0] + ps[il][1]);
            float* So = g_S + ((size_t)b * CL + i) * QL;
            float* Sr = g_Srow + ((size_t)b * CL + i) * QL;
#pragma unroll
            for (int ni = 0; ni < 8; ni++) {
                int j = n0w + ni * 8 + (c << 1);
                float v0 = acc[mi][ni][dh * 2], v1 = acc[mi][ni][dh * 2 + 1];
                *(float2*)(So + j) = make_float2(v0, v1);
                float e0 = __expf((sqm[j] ? v0 : NEG) - m) * inv;
                float e1 = __expf((sqm[j + 1] ? v1 : NEG) - m) * inv;
                *(float2*)(Sr + j) = make_float2(e0, e1);
            }
        }

    // ---- column-softmax partial stats (cmask over rows), per CTA tile ----
    int mw = wid & 3;
    {
        float cmx[8][2];
#pragma unroll
        for (int ni = 0; ni < 8; ni++) { cmx[ni][0] = NEG; cmx[ni][1] = NEG; }
#pragma unroll
        for (int mi = 0; mi < 2; mi++)
#pragma unroll
            for (int dh = 0; dh < 2; dh++) {
                int il = m0w + mi * 16 + r + dh * 8;
                bool ck = scm[il] != 0;
#pragma unroll
                for (int ni = 0; ni < 8; ni++) {
                    cmx[ni][0] = fmaxf(cmx[ni][0], ck ? acc[mi][ni][dh * 2] : NEG);
                    cmx[ni][1] = fmaxf(cmx[ni][1], ck ? acc[mi][ni][dh * 2 + 1] : NEG);
                }
            }
#pragma unroll
        for (int ni = 0; ni < 8; ni++)
#pragma unroll
            for (int jj = 0; jj < 2; jj++) {
                float v = cmx[ni][jj];
                v = fmaxf(v, __shfl_xor_sync(0xffffffffu, v, 4));
                v = fmaxf(v, __shfl_xor_sync(0xffffffffu, v, 8));
                v = fmaxf(v, __shfl_xor_sync(0xffffffffu, v, 16));
                cmx[ni][jj] = v;
            }
        if (r == 0) {
#pragma unroll
            for (int ni = 0; ni < 8; ni++) {
                int j = n0w + ni * 8 + (c << 1);
                cpm[mw][j] = cmx[ni][0];
                cpm[mw][j + 1] = cmx[ni][1];
            }
        }
    }
    __syncthreads();
    {
        float csm[8][2];
#pragma unroll
        for (int ni = 0; ni < 8; ni++) { csm[ni][0] = 0.f; csm[ni][1] = 0.f; }
        float Mj[8][2];
#pragma unroll
        for (int ni = 0; ni < 8; ni++)
#pragma unroll
            for (int jj = 0; jj < 2; jj++) {
                int j = n0w + ni * 8 + (c << 1) + jj;
                Mj[ni][jj] = fmaxf(fmaxf(cpm[0][j], cpm[1][j]), fmaxf(cpm[2][j], cpm[3][j]));
            }
#pragma unroll
        for (int mi = 0; mi < 2; mi++)
#pragma unroll
            for (int dh = 0; dh < 2; dh++) {
                int il = m0w + mi * 16 + r + dh * 8;
                bool ck = scm[il] != 0;
#pragma unroll
                for (int ni = 0; ni < 8; ni++) {
                    csm[ni][0] += ck ? __expf(acc[mi][ni][dh * 2] - Mj[ni][0]) : 0.f;
                    csm[ni][1] += ck ? __expf(acc[mi][ni][dh * 2 + 1] - Mj[ni][1]) : 0.f;
                }
            }
#pragma unroll
        for (int ni = 0; ni < 8; ni++)
#pragma unroll
            for (int jj = 0; jj < 2; jj++) {
                float v = csm[ni][jj];
                v += __shfl_xor_sync(0xffffffffu, v, 4);
                v += __shfl_xor_sync(0xffffffffu, v, 8);
                v += __shfl_xor_sync(0xffffffffu, v, 16);
                csm[ni][jj] = v;
            }
        if (r == 0) {
#pragma unroll
            for (int ni = 0; ni < 8; ni++) {
                int j = n0w + ni * 8 + (c << 1);
                cps[mw][j] = csm[ni][0];
                cps[mw][j + 1] = csm[ni][1];
            }
        }
    }
    __syncthreads();
    if (t < 128) {
        float M = fmaxf(fmaxf(cpm[0][t], cpm[1][t]), fmaxf(cpm[2][t], cpm[3][t]));
        float S_ = cps[0][t] + cps[1][t] + cps[2][t] + cps[3][t];
        int idx = (b * 8 + blockIdx.x) * QL + t;
        g_pmax[idx] = M;
        g_psum[idx] = S_;
    }
}

// ---------------------------------------------------------------------------
// K4': combine per-tile column partials -> g_cmax, g_cinv. Tiny.
// ---------------------------------------------------------------------------
__global__ void k_colcomb() {
    int b = blockIdx.x, j = threadIdx.x;
    float M = NEG;
#pragma unroll
    for (int tl = 0; tl < 8; tl++) M = fmaxf(M, g_pmax[(b * 8 + tl) * QL + j]);
    float S_ = 0.f;
#pragma unroll
    for (int tl = 0; tl < 8; tl++) {
        int idx = (b * 8 + tl) * QL + j;
        S_ += g_psum[idx] * __expf(g_pmax[idx] - M);
    }
    g_cmax[b * QL + j] = M;
    g_cinv[b * QL + j] = 1.f / S_;
}

// ---------------------------------------------------------------------------
// K5: T[j,h] = (1/s[j]) * sum_i [cm[i] ? exp(S[i,j]-m[j]) : 0] * C[i,h]
// 256 threads, 8 warps 4(m=j) x 2(n=h), warp tile 32x128, CTA tile 128x256.
// Halves g_S re-reads vs n=128 tiling. Kc=16 double-buffered.
// ---------------------------------------------------------------------------
__global__ __launch_bounds__(256) void k_tgemm(const float* __restrict__ C,
                                               const int* __restrict__ cmask) {
    __shared__ float Ss[2][16][136];
    __shared__ float Cs[2][16][264];
    __shared__ float smax[128], sinv[128];
    int b = blockIdx.z, h0 = blockIdx.y * 256;
    int t = threadIdx.x, lane = t & 31, wid = t >> 5;
    int m0w = (wid & 3) * 32, n0w = (wid >> 2) * 128;
    int r = lane >> 2, c = lane & 3;
    const float* Sb = g_S + (size_t)b * CL * QL;
    const float* Cb = C + (size_t)b * CL * HH;
    const int* cm = cmask + b * CL;
    int si = t >> 5, sj = (t & 31) * 4;   // A fill: rows si, si+8
    int ci = t >> 4, ch = (t & 15) * 16;  // B fill: row ci, 16 cols (4 float4)

    if (t < 128) {
        smax[t] = g_cmax[b * QL + t];
        sinv[t] = g_cinv[b * QL + t];
    }
    __syncthreads();
    float4 msj = *(const float4*)(smax + sj);

    float4 s1, s2, c1, c2, c3, c4;
    int cm0, cm1;
    s1 = *(const float4*)(Sb + (size_t)si * QL + sj);
    s2 = *(const float4*)(Sb + (size_t)(si + 8) * QL + sj);
    c1 = *(const float4*)(Cb + (size_t)ci * HH + h0 + ch);
    c2 = *(const float4*)(Cb + (size_t)ci * HH + h0 + ch + 4);
    c3 = *(const float4*)(Cb + (size_t)ci * HH + h0 + ch + 8);
    c4 = *(const float4*)(Cb + (size_t)ci * HH + h0 + ch + 12);
    cm0 = cm[si];
    cm1 = cm[si + 8];
    {
        float4 e1 = cm0 ? make_float4(__expf(s1.x - msj.x), __expf(s1.y - msj.y),
                                      __expf(s1.z - msj.z), __expf(s1.w - msj.w))
                        : make_float4(0.f, 0.f, 0.f, 0.f);
        float4 e2 = cm1 ? make_float4(__expf(s2.x - msj.x), __expf(s2.y - msj.y),
                                      __expf(s2.z - msj.z), __expf(s2.w - msj.w))
                        : make_float4(0.f, 0.f, 0.f, 0.f);
        *(float4*)&Ss[0][si][sj] = tf4(e1);
        *(float4*)&Ss[0][si + 8][sj] = tf4(e2);
        *(float4*)&Cs[0][ci][ch] = tf4(c1);
        *(float4*)&Cs[0][ci][ch + 4] = tf4(c2);
        *(float4*)&Cs[0][ci][ch + 8] = tf4(c3);
        *(float4*)&Cs[0][ci][ch + 12] = tf4(c4);
    }
    __syncthreads();

    float acc[2][16][4] = {};
    for (int kk = 0; kk < CL; kk += 16) {
        int cur = (kk >> 4) & 1;
        bool more = (kk + 16) < CL;
        if (more) {
            int k2 = kk + 16;
            s1 = *(const float4*)(Sb + (size_t)(k2 + si) * QL + sj);
            s2 = *(const float4*)(Sb + (size_t)(k2 + si + 8) * QL + sj);
            c1 = *(const float4*)(Cb + (size_t)(k2 + ci) * HH + h0 + ch);
            c2 = *(const float4*)(Cb + (size_t)(k2 + ci) * HH + h0 + ch + 4);
            c3 = *(const float4*)(Cb + (size_t)(k2 + ci) * HH + h0 + ch + 8);
            c4 = *(const float4*)(Cb + (size_t)(k2 + ci) * HH + h0 + ch + 12);
            cm0 = cm[k2 + si];
            cm1 = cm[k2 + si + 8];
        }
#pragma unroll
        for (int h = 0; h < 2; h++) {
            int ck = h * 8 + c;
            uint32_t af[2][4];
#pragma unroll
            for (int mi = 0; mi < 2; mi++) {
                int mb = m0w + mi * 16;
                af[mi][0] = __float_as_uint(Ss[cur][ck][mb + r]);
                af[mi][1] = __float_as_uint(Ss[cur][ck][mb + r + 8]);
                af[mi][2] = __float_as_uint(Ss[cur][ck + 4][mb + r]);
                af[mi][3] = __float_as_uint(Ss[cur][ck + 4][mb + r + 8]);
            }
#pragma unroll
            for (int ni = 0; ni < 16; ni++) {
                int nb = n0w + ni * 8 + r;
                uint32_t bf[2];
                bf[0] = __float_as_uint(Cs[cur][ck][nb]);
                bf[1] = __float_as_uint(Cs[cur][ck + 4][nb]);
                mma8(acc[0][ni], af[0], bf);
                mma8(acc[1][ni], af[1], bf);
            }
        }
        if (more) {
            int nxt = cur ^ 1;
            float4 e1 = cm0 ? make_float4(__expf(s1.x - msj.x), __expf(s1.y - msj.y),
                                          __expf(s1.z - msj.z), __expf(s1.w - msj.w))
                            : make_float4(0.f, 0.f, 0.f, 0.f);
            float4 e2 = cm1 ? make_float4(__expf(s2.x - msj.x), __expf(s2.y - msj.y),
                                          __expf(s2.z - msj.z), __expf(s2.w - msj.w))
                            : make_float4(0.f, 0.f, 0.f, 0.f);
            *(float4*)&Ss[nxt][si][sj] = tf4(e1);
            *(float4*)&Ss[nxt][si + 8][sj] = tf4(e2);
            *(float4*)&Cs[nxt][ci][ch] = tf4(c1);
            *(float4*)&Cs[nxt][ci][ch + 4] = tf4(c2);
            *(float4*)&Cs[nxt][ci][ch + 8] = tf4(c3);
            *(float4*)&Cs[nxt][ci][ch + 12] = tf4(c4);
        }
        __syncthreads();
    }
#pragma unroll
    for (int mi = 0; mi < 2; mi++)
#pragma unroll
        for (int dh = 0; dh < 2; dh++) {
            int jl = m0w + mi * 16 + r + dh * 8;
            float inv = sinv[jl];
            float* To = g_T + ((size_t)b * QL + jl) * HH + h0;
#pragma unroll
            for (int ni = 0; ni < 16; ni++) {
                int h = n0w + ni * 8 + (c << 1);
                *(float2*)(To + h) = make_float2(acc[mi][ni][dh * 2] * inv,
                                                 acc[mi][ni][dh * 2 + 1] * inv);
            }
        }
}

// ---------------------------------------------------------------------------
// K6: fused A = Srow@Q and Bm = Srow@T (K=128), writes concat output.
// 512 threads, 16 warps 4(m) x 4(n), warp 32x32, tile 128x128, dyn smem 55296B.
// Best measured config (R8/R11: ~120us healthy clock).
// ---------------------------------------------------------------------------
#define K6_AS(bu, i, k) dsm[(bu) * 2560 + (i) * 20 + (k)]
#define K6_QS(bu, k, n) dsm[5120 + (bu) * 2176 + (k) * 136 + (n)]
#define K6_TS(bu, k, n) dsm[9472 + (bu) * 2176 + (k) * 136 + (n)]

__global__ __launch_bounds__(512) void k_out(const float* __restrict__ C,
                                             const float* __restrict__ Q,
                                             float* __restrict__ out) {
    extern __shared__ float dsm[];
    int b = blockIdx.z, i0 = blockIdx.x * 128, h0 = blockIdx.y * 128;
    int t = threadIdx.x, lane = t & 31, wid = t >> 5;
    int m0w = (wid & 3) * 32, n0w = (wid >> 2) * 32;
    int r = lane >> 2, c = lane & 3;
    const float* Sr = g_Srow + ((size_t)b * CL + i0) * QL;
    const float* Qb = Q + (size_t)b * QL * HH;
    const float* Tb = g_T + (size_t)b * QL * HH;
    int lr = t >> 2, lk = (t & 3) * 4;
    int kr = t >> 5, nc = (t & 31) * 4;

    float4 av, qv, tv;
    av = *(const float4*)(Sr + (size_t)lr * QL + lk);
    qv = *(const float4*)(Qb + (size_t)kr * HH + h0 + nc);
    tv = *(const float4*)(Tb + (size_t)kr * HH + h0 + nc);
    *(float4*)&K6_AS(0, lr, lk) = tf4(av);
    *(float4*)&K6_QS(0, kr, nc) = tf4(qv);
    *(float4*)&K6_TS(0, kr, nc) = tf4(tv);
    __syncthreads();

    float accA[2][4][4] = {}, accB[2][4][4] = {};
    for (int kk = 0; kk < QL; kk += 16) {
        int cur = (kk >> 4) & 1;
        bool more = (kk + 16) < QL;
        if (more) {
            int k2 = kk + 16;
            av = *(const float4*)(Sr + (size_t)lr * QL + k2 + lk);
            qv = *(const float4*)(Qb + (size_t)(k2 + kr) * HH + h0 + nc);
            tv = *(const float4*)(Tb + (size_t)(k2 + kr) * HH + h0 + nc);
        }
#pragma unroll
        for (int h = 0; h < 2; h++) {
            int ck = h * 8 + c;
            uint32_t af[2][4], bq[4][2], bt[4][2];
#pragma unroll
            for (int mi = 0; mi < 2; mi++) {
                int mb = m0w + mi * 16;
                af[mi][0] = __float_as_uint(K6_AS(cur, mb + r, ck));
                af[mi][1] = __float_as_uint(K6_AS(cur, mb + r + 8, ck));
                af[mi][2] = __float_as_uint(K6_AS(cur, mb + r, ck + 4));
                af[mi][3] = __float_as_uint(K6_AS(cur, mb + r + 8, ck + 4));
            }
#pragma unroll
            for (int ni = 0; ni < 4; ni++) {
                int nb = n0w + ni * 8 + r;
                bq[ni][0] = __float_as_uint(K6_QS(cur, ck, nb));
                bq[ni][1] = __float_as_uint(K6_QS(cur, ck + 4, nb));
                bt[ni][0] = __float_as_uint(K6_TS(cur, ck, nb));
                bt[ni][1] = __float_as_uint(K6_TS(cur, ck + 4, nb));
            }
#pragma unroll
            for (int mi = 0; mi < 2; mi++)
#pragma unroll
                for (int ni = 0; ni < 4; ni++) {
                    mma8(accA[mi][ni], af[mi], bq[ni]);
                    mma8(accB[mi][ni], af[mi], bt[ni]);
                }
        }
        if (more) {
            int nxt = cur ^ 1;
            *(float4*)&K6_AS(nxt, lr, lk) = tf4(av);
            *(float4*)&K6_QS(nxt, kr, nc) = tf4(qv);
            *(float4*)&K6_TS(nxt, kr, nc) = tf4(tv);
        }
        __syncthreads();
    }
    const float* Cb = C + (size_t)b * CL * HH;
#pragma unroll
    for (int mi = 0; mi < 2; mi++)
#pragma unroll
        for (int dh = 0; dh < 2; dh++) {
            int i = i0 + m0w + mi * 16 + r + dh * 8;
            const float* Crow = Cb + (size_t)i * HH;
            float* ob = out + ((size_t)b * CL + i) * (4 * HH);
#pragma unroll
            for (int ni = 0; ni < 4; ni++) {
                int h = h0 + n0w + ni * 8 + (c << 1);
                float2 cv = *(const float2*)(Crow + h);
                float2 a2 = make_float2(accA[mi][ni][dh * 2], accA[mi][ni][dh * 2 + 1]);
                float2 b2 = make_float2(accB[mi][ni][dh * 2], accB[mi][ni][dh * 2 + 1]);
                *(float2*)(ob + h) = cv;
                *(float2*)(ob + HH + h) = a2;
                *(float2*)(ob + 2 * HH + h) = make_float2(cv.x * a2.x, cv.y * a2.y);
                *(float2*)(ob + 3 * HH + h) = make_float2(cv.x * b2.x, cv.y * b2.y);
            }
        }
}

// ---------------------------------------------------------------------------
extern "C" void kernel_launch(void* const* d_in, const int* in_sizes, int n_in,
                              void* d_out, int out_size) {
    const float* C = (const float*)d_in[0];
    const float* Q = (const float*)d_in[1];
    const int* cmask = (const int*)d_in[2];
    const int* qmask = (const int*)d_in[3];
    const float* w = (const float*)d_in[4];
    const float* bias = (const float*)d_in[5];
    float* out = (float*)d_out;

    static bool attr_done = false;
    if (!attr_done) {
        cudaFuncSetAttribute(k_out, cudaFuncAttributeMaxDynamicSharedMemorySize, 55296);
        attr_done = true;
    }

    k_sgemm<<<dim3(8, 1, BB), 256>>>(C, Q, w, bias, qmask, cmask);
    k_colcomb<<<BB, 128>>>();
    k_tgemm<<<dim3(1, 2, BB), 256>>>(C, cmask);
    k_out<<<dim3(8, 4, BB), 512, 55296>>>(C, Q, out);
}

// round 17
// speedup vs baseline: 1.4215x; 1.1593x over previous
#include <cuda_runtime.h>
#include <cstdint>

#define BB 32
#define CL 1024
#define QL 128
#define HH 512
#define NEG (-1e30f)

// ---- scratch (device globals; no allocations allowed) ----
__device__ float g_S[(size_t)BB * CL * QL];     // raw scores
__device__ float g_Srow[(size_t)BB * CL * QL];  // row softmax
__device__ float g_T[(size_t)BB * QL * HH];     // T = Scol^T @ C (scaled)
__device__ float g_pmax[BB * 8 * QL];           // per-(b, i-tile) col max
__device__ float g_psum[BB * 8 * QL];           // per-(b, i-tile) col sum
__device__ float g_cmax[BB * QL];               // col-softmax max per j
__device__ float g_cinv[BB * QL];               // 1 / col-softmax sum per j

__device__ __forceinline__ float tf32r(float x) {
    uint32_t u;
    asm("cvt.rna.tf32.f32 %0, %1;\n" : "=r"(u) : "f"(x));
    return __uint_as_float(u);
}
__device__ __forceinline__ float4 tf4(float4 v) {
    return make_float4(tf32r(v.x), tf32r(v.y), tf32r(v.z), tf32r(v.w));
}
__device__ __forceinline__ float dot4(float4 a, float4 b) {
    return a.x * b.x + a.y * b.y + a.z * b.z + a.w * b.w;
}
// pack two floats into bf16x2 (lo arg -> low half = first/even k element)
__device__ __forceinline__ uint32_t pk(float lo, float hi) {
    uint32_t d;
    asm("cvt.rn.bf16x2.f32 %0, %1, %2;" : "=r"(d) : "f"(hi), "f"(lo));
    return d;
}

__device__ __forceinline__ void mma8(float* d, const uint32_t* a, const uint32_t* b) {
    asm volatile(
        "mma.sync.aligned.m16n8k8.row.col.f32.tf32.tf32.f32 "
        "{%0,%1,%2,%3},{%4,%5,%6,%7},{%8,%9},{%0,%1,%2,%3};\n"
        : "+f"(d[0]), "+f"(d[1]), "+f"(d[2]), "+f"(d[3])
        : "r"(a[0]), "r"(a[1]), "r"(a[2]), "r"(a[3]), "r"(b[0]), "r"(b[1]));
}
__device__ __forceinline__ void mma16(float* d, const uint32_t* a, const uint32_t* b) {
    asm volatile(
        "mma.sync.aligned.m16n8k16.row.col.f32.bf16.bf16.f32 "
        "{%0,%1,%2,%3},{%4,%5,%6,%7},{%8,%9},{%0,%1,%2,%3};\n"
        : "+f"(d[0]), "+f"(d[1]), "+f"(d[2]), "+f"(d[3])
        : "r"(a[0]), "r"(a[1]), "r"(a[2]), "r"(a[3]), "r"(b[0]), "r"(b[1]));
}

// ---------------------------------------------------------------------------
// K2: S = (C*w3)@Q^T + (C@w1)[i] + (Q@w2)[j] + b.
// Fused epilogues: row-softmax (qmask) AND per-CTA column stats (cmask).
// 256 threads, tile 128(i) x 128(j), Kc=16 double-buffered, warps 4x2 (32x64).
// ---------------------------------------------------------------------------
__global__ __launch_bounds__(256) void k_sgemm(const float* __restrict__ C,
                                               const float* __restrict__ Q,
                                               const float* __restrict__ w,
                                               const float* __restrict__ bias,
                                               const int* __restrict__ qmask,
                                               const int* __restrict__ cmask) {
    __shared__ float As[2][128][20];
    __shared__ float Bs[2][128][20];
    __shared__ float scw1[128], sqw2[128];
    __shared__ int sqm[128], scm[128];
    __shared__ float pm[128][2], ps[128][2];
    __shared__ float cpm[4][128], cps[4][128];

    int b = blockIdx.z, i0 = blockIdx.x * 128;
    int t = threadIdx.x, lane = t & 31, wid = t >> 5;
    int m0w = (wid & 3) * 32, n0w = (wid >> 2) * 64;
    int r = lane >> 2, c = lane & 3;
    const float* w1 = w;
    const float* w2 = w + HH;
    const float* w3 = w + 2 * HH;
    const float* Cb = C + ((size_t)b * CL + i0) * HH;
    const float* Qb = Q + (size_t)b * QL * HH;
    int lr = t >> 1, lk = (t & 1) * 8;

    if (t < 128) {
        sqm[t] = qmask[b * QL + t];
        scm[t] = cmask[b * CL + i0 + t];
    }

    float cwacc = 0.f, qwacc = 0.f;
    float4 a1, a2, q1, q2, w3a, w3b;
    a1 = *(const float4*)(Cb + (size_t)lr * HH + lk);
    a2 = *(const float4*)(Cb + (size_t)lr * HH + lk + 4);
    q1 = *(const float4*)(Qb + (size_t)lr * HH + lk);
    q2 = *(const float4*)(Qb + (size_t)lr * HH + lk + 4);
    w3a = *(const float4*)(w3 + lk);
    w3b = *(const float4*)(w3 + lk + 4);
    cwacc += dot4(a1, *(const float4*)(w1 + lk)) + dot4(a2, *(const float4*)(w1 + lk + 4));
    qwacc += dot4(q1, *(const float4*)(w2 + lk)) + dot4(q2, *(const float4*)(w2 + lk + 4));
    *(float4*)&As[0][lr][lk] = make_float4(tf32r(a1.x * w3a.x), tf32r(a1.y * w3a.y),
                                           tf32r(a1.z * w3a.z), tf32r(a1.w * w3a.w));
    *(float4*)&As[0][lr][lk + 4] = make_float4(tf32r(a2.x * w3b.x), tf32r(a2.y * w3b.y),
                                               tf32r(a2.z * w3b.z), tf32r(a2.w * w3b.w));
    *(float4*)&Bs[0][lr][lk] = tf4(q1);
    *(float4*)&Bs[0][lr][lk + 4] = tf4(q2);
    __syncthreads();

    float acc[2][8][4] = {};
    for (int kk = 0; kk < HH; kk += 16) {
        int cur = (kk >> 4) & 1;
        bool more = (kk + 16) < HH;
        if (more) {
            int k2 = kk + 16;
            a1 = *(const float4*)(Cb + (size_t)lr * HH + k2 + lk);
            a2 = *(const float4*)(Cb + (size_t)lr * HH + k2 + lk + 4);
            q1 = *(const float4*)(Qb + (size_t)lr * HH + k2 + lk);
            q2 = *(const float4*)(Qb + (size_t)lr * HH + k2 + lk + 4);
            w3a = *(const float4*)(w3 + k2 + lk);
            w3b = *(const float4*)(w3 + k2 + lk + 4);
            cwacc += dot4(a1, *(const float4*)(w1 + k2 + lk)) +
                     dot4(a2, *(const float4*)(w1 + k2 + lk + 4));
            qwacc += dot4(q1, *(const float4*)(w2 + k2 + lk)) +
                     dot4(q2, *(const float4*)(w2 + k2 + lk + 4));
        }
#pragma unroll
        for (int h = 0; h < 2; h++) {
            int ck = h * 8 + c;
            uint32_t af[2][4], bf[8][2];
#pragma unroll
            for (int mi = 0; mi < 2; mi++) {
                int mb = m0w + mi * 16;
                af[mi][0] = __float_as_uint(As[cur][mb + r][ck]);
                af[mi][1] = __float_as_uint(As[cur][mb + r + 8][ck]);
                af[mi][2] = __float_as_uint(As[cur][mb + r][ck + 4]);
                af[mi][3] = __float_as_uint(As[cur][mb + r + 8][ck + 4]);
            }
#pragma unroll
            for (int ni = 0; ni < 8; ni++) {
                int nb = n0w + ni * 8 + r;
                bf[ni][0] = __float_as_uint(Bs[cur][nb][ck]);
                bf[ni][1] = __float_as_uint(Bs[cur][nb][ck + 4]);
            }
#pragma unroll
            for (int mi = 0; mi < 2; mi++)
#pragma unroll
                for (int ni = 0; ni < 8; ni++) mma8(acc[mi][ni], af[mi], bf[ni]);
        }
        if (more) {
            int nxt = cur ^ 1;
            *(float4*)&As[nxt][lr][lk] = make_float4(tf32r(a1.x * w3a.x), tf32r(a1.y * w3a.y),
                                                     tf32r(a1.z * w3a.z), tf32r(a1.w * w3a.w));
            *(float4*)&As[nxt][lr][lk + 4] = make_float4(tf32r(a2.x * w3b.x), tf32r(a2.y * w3b.y),
                                                         tf32r(a2.z * w3b.z), tf32r(a2.w * w3b.w));
            *(float4*)&Bs[nxt][lr][lk] = tf4(q1);
            *(float4*)&Bs[nxt][lr][lk + 4] = tf4(q2);
        }
        __syncthreads();
    }

    cwacc += __shfl_xor_sync(0xffffffffu, cwacc, 1);
    qwacc += __shfl_xor_sync(0xffffffffu, qwacc, 1);
    if ((t & 1) == 0) { scw1[lr] = cwacc; sqw2[lr] = qwacc; }
    __syncthreads();

    float b0 = bias[0];
    int nhalf = wid >> 2;
    float qw[8][2];
#pragma unroll
    for (int ni = 0; ni < 8; ni++) {
        int j = n0w + ni * 8 + (c << 1);
        qw[ni][0] = sqw2[j];
        qw[ni][1] = sqw2[j + 1];
    }
#pragma unroll
    for (int mi = 0; mi < 2; mi++)
#pragma unroll
        for (int dh = 0; dh < 2; dh++) {
            float cw = scw1[m0w + mi * 16 + r + dh * 8] + b0;
#pragma unroll
            for (int ni = 0; ni < 8; ni++) {
                acc[mi][ni][dh * 2 + 0] += cw + qw[ni][0];
                acc[mi][ni][dh * 2 + 1] += cw + qw[ni][1];
            }
        }
    // ---- row softmax (qmask) ----
#pragma unroll
    for (int mi = 0; mi < 2; mi++)
#pragma unroll
        for (int dh = 0; dh < 2; dh++) {
            int il = m0w + mi * 16 + r + dh * 8;
            float mx = NEG;
#pragma unroll
            for (int ni = 0; ni < 8; ni++) {
                int j = n0w + ni * 8 + (c << 1);
                mx = fmaxf(mx, sqm[j] ? acc[mi][ni][dh * 2] : NEG);
                mx = fmaxf(mx, sqm[j + 1] ? acc[mi][ni][dh * 2 + 1] : NEG);
            }
            mx = fmaxf(mx, __shfl_xor_sync(0xffffffffu, mx, 1));
            mx = fmaxf(mx, __shfl_xor_sync(0xffffffffu, mx, 2));
            if (c == 0) pm[il][nhalf] = mx;
        }
    __syncthreads();
    float m2[2][2];
#pragma unroll
    for (int mi = 0; mi < 2; mi++)
#pragma unroll
        for (int dh = 0; dh < 2; dh++) {
            int il = m0w + mi * 16 + r + dh * 8;
            float m = fmaxf(pm[il][0], pm[il][1]);
            m2[mi][dh] = m;
            float sum = 0.f;
#pragma unroll
            for (int ni = 0; ni < 8; ni++) {
                int j = n0w + ni * 8 + (c << 1);
                float x0 = sqm[j] ? acc[mi][ni][dh * 2] : NEG;
                float x1 = sqm[j + 1] ? acc[mi][ni][dh * 2 + 1] : NEG;
                sum += __expf(x0 - m) + __expf(x1 - m);
            }
            sum += __shfl_xor_sync(0xffffffffu, sum, 1);
            sum += __shfl_xor_sync(0xffffffffu, sum, 2);
            if (c == 0) ps[il][nhalf] = sum;
        }
    __syncthreads();
#pragma unroll
    for (int mi = 0; mi < 2; mi++)
#pragma unroll
        for (int dh = 0; dh < 2; dh++) {
            int il = m0w + mi * 16 + r + dh * 8;
            int i = i0 + il;
            float m = m2[mi][dh];
            float inv = 1.f / (ps[il][0] + ps[il][1]);
            float* So = g_S + ((size_t)b * CL + i) * QL;
            float* Sr = g_Srow + ((size_t)b * CL + i) * QL;
#pragma unroll
            for (int ni = 0; ni < 8; ni++) {
                int j = n0w + ni * 8 + (c << 1);
                float v0 = acc[mi][ni][dh * 2], v1 = acc[mi][ni][dh * 2 + 1];
                *(float2*)(So + j) = make_float2(v0, v1);
                float e0 = __expf((sqm[j] ? v0 : NEG) - m) * inv;
                float e1 = __expf((sqm[j + 1] ? v1 : NEG) - m) * inv;
                *(float2*)(Sr + j) = make_float2(e0, e1);
            }
        }

    // ---- column-softmax partial stats (cmask over rows), per CTA tile ----
    int mw = wid & 3;
    {
        float cmx[8][2];
#pragma unroll
        for (int ni = 0; ni < 8; ni++) { cmx[ni][0] = NEG; cmx[ni][1] = NEG; }
#pragma unroll
        for (int mi = 0; mi < 2; mi++)
#pragma unroll
            for (int dh = 0; dh < 2; dh++) {
                int il = m0w + mi * 16 + r + dh * 8;
                bool ck = scm[il] != 0;
#pragma unroll
                for (int ni = 0; ni < 8; ni++) {
                    cmx[ni][0] = fmaxf(cmx[ni][0], ck ? acc[mi][ni][dh * 2] : NEG);
                    cmx[ni][1] = fmaxf(cmx[ni][1], ck ? acc[mi][ni][dh * 2 + 1] : NEG);
                }
            }
#pragma unroll
        for (int ni = 0; ni < 8; ni++)
#pragma unroll
            for (int jj = 0; jj < 2; jj++) {
                float v = cmx[ni][jj];
                v = fmaxf(v, __shfl_xor_sync(0xffffffffu, v, 4));
                v = fmaxf(v, __shfl_xor_sync(0xffffffffu, v, 8));
                v = fmaxf(v, __shfl_xor_sync(0xffffffffu, v, 16));
                cmx[ni][jj] = v;
            }
        if (r == 0) {
#pragma unroll
            for (int ni = 0; ni < 8; ni++) {
                int j = n0w + ni * 8 + (c << 1);
                cpm[mw][j] = cmx[ni][0];
                cpm[mw][j + 1] = cmx[ni][1];
            }
        }
    }
    __syncthreads();
    {
        float csm[8][2];
#pragma unroll
        for (int ni = 0; ni < 8; ni++) { csm[ni][0] = 0.f; csm[ni][1] = 0.f; }
        float Mj[8][2];
#pragma unroll
        for (int ni = 0; ni < 8; ni++)
#pragma unroll
            for (int jj = 0; jj < 2; jj++) {
                int j = n0w + ni * 8 + (c << 1) + jj;
                Mj[ni][jj] = fmaxf(fmaxf(cpm[0][j], cpm[1][j]), fmaxf(cpm[2][j], cpm[3][j]));
            }
#pragma unroll
        for (int mi = 0; mi < 2; mi++)
#pragma unroll
            for (int dh = 0; dh < 2; dh++) {
                int il = m0w + mi * 16 + r + dh * 8;
                bool ck = scm[il] != 0;
#pragma unroll
                for (int ni = 0; ni < 8; ni++) {
                    csm[ni][0] += ck ? __expf(acc[mi][ni][dh * 2] - Mj[ni][0]) : 0.f;
                    csm[ni][1] += ck ? __expf(acc[mi][ni][dh * 2 + 1] - Mj[ni][1]) : 0.f;
                }
            }
#pragma unroll
        for (int ni = 0; ni < 8; ni++)
#pragma unroll
            for (int jj = 0; jj < 2; jj++) {
                float v = csm[ni][jj];
                v += __shfl_xor_sync(0xffffffffu, v, 4);
                v += __shfl_xor_sync(0xffffffffu, v, 8);
                v += __shfl_xor_sync(0xffffffffu, v, 16);
                csm[ni][jj] = v;
            }
        if (r == 0) {
#pragma unroll
            for (int ni = 0; ni < 8; ni++) {
                int j = n0w + ni * 8 + (c << 1);
                cps[mw][j] = csm[ni][0];
                cps[mw][j + 1] = csm[ni][1];
            }
        }
    }
    __syncthreads();
    if (t < 128) {
        float M = fmaxf(fmaxf(cpm[0][t], cpm[1][t]), fmaxf(cpm[2][t], cpm[3][t]));
        float S_ = cps[0][t] + cps[1][t] + cps[2][t] + cps[3][t];
        int idx = (b * 8 + blockIdx.x) * QL + t;
        g_pmax[idx] = M;
        g_psum[idx] = S_;
    }
}

// ---------------------------------------------------------------------------
// K4': combine per-tile column partials -> g_cmax, g_cinv. Tiny.
// ---------------------------------------------------------------------------
__global__ void k_colcomb() {
    int b = blockIdx.x, j = threadIdx.x;
    float M = NEG;
#pragma unroll
    for (int tl = 0; tl < 8; tl++) M = fmaxf(M, g_pmax[(b * 8 + tl) * QL + j]);
    float S_ = 0.f;
#pragma unroll
    for (int tl = 0; tl < 8; tl++) {
        int idx = (b * 8 + tl) * QL + j;
        S_ += g_psum[idx] * __expf(g_pmax[idx] - M);
    }
    g_cmax[b * QL + j] = M;
    g_cinv[b * QL + j] = 1.f / S_;
}

// ---------------------------------------------------------------------------
// K5: T[j,h] = (1/s[j]) * sum_i [cm[i] ? exp(S[i,j]-m[j]) : 0] * C[i,h]
// 256 threads, 8 warps 4(m=j) x 2(n=h), warp 32x64, tile 128x128, Kc=16.
// ---------------------------------------------------------------------------
__global__ __launch_bounds__(256) void k_tgemm(const float* __restrict__ C,
                                               const int* __restrict__ cmask) {
    __shared__ float Ss[2][16][136];
    __shared__ float Cs[2][16][136];
    __shared__ float smax[128], sinv[128];
    int b = blockIdx.z, h0 = blockIdx.y * 128;
    int t = threadIdx.x, lane = t & 31, wid = t >> 5;
    int m0w = (wid & 3) * 32, n0w = (wid >> 2) * 64;
    int r = lane >> 2, c = lane & 3;
    const float* Sb = g_S + (size_t)b * CL * QL;
    const float* Cb = C + (size_t)b * CL * HH;
    const int* cm = cmask + b * CL;
    int si = t >> 5, sj = (t & 31) * 4;
    int ci = t >> 4, ch = (t & 15) * 8;

    if (t < 128) {
        smax[t] = g_cmax[b * QL + t];
        sinv[t] = g_cinv[b * QL + t];
    }
    __syncthreads();
    float4 msj = *(const float4*)(smax + sj);

    float4 s1, s2, c1, c2;
    int cm0, cm1;
    s1 = *(const float4*)(Sb + (size_t)si * QL + sj);
    s2 = *(const float4*)(Sb + (size_t)(si + 8) * QL + sj);
    c1 = *(const float4*)(Cb + (size_t)ci * HH + h0 + ch);
    c2 = *(const float4*)(Cb + (size_t)ci * HH + h0 + ch + 4);
    cm0 = cm[si];
    cm1 = cm[si + 8];
    {
        float4 e1 = cm0 ? make_float4(__expf(s1.x - msj.x), __expf(s1.y - msj.y),
                                      __expf(s1.z - msj.z), __expf(s1.w - msj.w))
                        : make_float4(0.f, 0.f, 0.f, 0.f);
        float4 e2 = cm1 ? make_float4(__expf(s2.x - msj.x), __expf(s2.y - msj.y),
                                      __expf(s2.z - msj.z), __expf(s2.w - msj.w))
                        : make_float4(0.f, 0.f, 0.f, 0.f);
        *(float4*)&Ss[0][si][sj] = tf4(e1);
        *(float4*)&Ss[0][si + 8][sj] = tf4(e2);
        *(float4*)&Cs[0][ci][ch] = tf4(c1);
        *(float4*)&Cs[0][ci][ch + 4] = tf4(c2);
    }
    __syncthreads();

    float acc[2][8][4] = {};
    for (int kk = 0; kk < CL; kk += 16) {
        int cur = (kk >> 4) & 1;
        bool more = (kk + 16) < CL;
        if (more) {
            int k2 = kk + 16;
            s1 = *(const float4*)(Sb + (size_t)(k2 + si) * QL + sj);
            s2 = *(const float4*)(Sb + (size_t)(k2 + si + 8) * QL + sj);
            c1 = *(const float4*)(Cb + (size_t)(k2 + ci) * HH + h0 + ch);
            c2 = *(const float4*)(Cb + (size_t)(k2 + ci) * HH + h0 + ch + 4);
            cm0 = cm[k2 + si];
            cm1 = cm[k2 + si + 8];
        }
#pragma unroll
        for (int h = 0; h < 2; h++) {
            int ck = h * 8 + c;
            uint32_t af[2][4], bf[8][2];
#pragma unroll
            for (int mi = 0; mi < 2; mi++) {
                int mb = m0w + mi * 16;
                af[mi][0] = __float_as_uint(Ss[cur][ck][mb + r]);
                af[mi][1] = __float_as_uint(Ss[cur][ck][mb + r + 8]);
                af[mi][2] = __float_as_uint(Ss[cur][ck + 4][mb + r]);
                af[mi][3] = __float_as_uint(Ss[cur][ck + 4][mb + r + 8]);
            }
#pragma unroll
            for (int ni = 0; ni < 8; ni++) {
                int nb = n0w + ni * 8 + r;
                bf[ni][0] = __float_as_uint(Cs[cur][ck][nb]);
                bf[ni][1] = __float_as_uint(Cs[cur][ck + 4][nb]);
            }
#pragma unroll
            for (int mi = 0; mi < 2; mi++)
#pragma unroll
                for (int ni = 0; ni < 8; ni++) mma8(acc[mi][ni], af[mi], bf[ni]);
        }
        if (more) {
            int nxt = cur ^ 1;
            float4 e1 = cm0 ? make_float4(__expf(s1.x - msj.x), __expf(s1.y - msj.y),
                                          __expf(s1.z - msj.z), __expf(s1.w - msj.w))
                            : make_float4(0.f, 0.f, 0.f, 0.f);
            float4 e2 = cm1 ? make_float4(__expf(s2.x - msj.x), __expf(s2.y - msj.y),
                                          __expf(s2.z - msj.z), __expf(s2.w - msj.w))
                            : make_float4(0.f, 0.f, 0.f, 0.f);
            *(float4*)&Ss[nxt][si][sj] = tf4(e1);
            *(float4*)&Ss[nxt][si + 8][sj] = tf4(e2);
            *(float4*)&Cs[nxt][ci][ch] = tf4(c1);
            *(float4*)&Cs[nxt][ci][ch + 4] = tf4(c2);
        }
        __syncthreads();
    }
#pragma unroll
    for (int mi = 0; mi < 2; mi++)
#pragma unroll
        for (int dh = 0; dh < 2; dh++) {
            int jl = m0w + mi * 16 + r + dh * 8;
            float inv = sinv[jl];
            float* To = g_T + ((size_t)b * QL + jl) * HH + h0;
#pragma unroll
            for (int ni = 0; ni < 8; ni++) {
                int h = n0w + ni * 8 + (c << 1);
                *(float2*)(To + h) = make_float2(acc[mi][ni][dh * 2] * inv,
                                                 acc[mi][ni][dh * 2 + 1] * inv);
            }
        }
}

// ---------------------------------------------------------------------------
// K6: fused A = Srow@Q and Bm = Srow@T via bf16 m16n8k16 (fp32 accum).
// 512 threads, 16 warps 4(m) x 4(n), warp 32x32, tile 128x128.
// Whole K=128 staged once in smem as bf16x2. No in-loop barriers.
// dyn smem = 3 * 128 * 68 * 4 = 104448 B.
// ---------------------------------------------------------------------------
#define AW 68

__global__ __launch_bounds__(512) void k_out(const float* __restrict__ C,
                                             const float* __restrict__ Q,
                                             float* __restrict__ out) {
    extern __shared__ uint32_t dsm32[];
    uint32_t* A32 = dsm32;                  // [128][AW]  Srow (bf16x2 pairs along k)
    uint32_t* Q32 = dsm32 + 128 * AW;       // [128][AW]  Q^T  [h][kp]
    uint32_t* T32 = dsm32 + 2 * 128 * AW;   // [128][AW]  T^T  [h][kp]
    int b = blockIdx.z, i0 = blockIdx.x * 128, h0 = blockIdx.y * 128;
    int t = threadIdx.x, lane = t & 31, wid = t >> 5;
    int m0w = (wid & 3) * 32, n0w = (wid >> 2) * 32;
    int r = lane >> 2, c = lane & 3;
    const float* Sr = g_Srow + ((size_t)b * CL + i0) * QL;
    const float* Qb = Q + (size_t)b * QL * HH;
    const float* Tb = g_T + (size_t)b * QL * HH;

    // ---- fill A: Srow rows (pairs along k are contiguous) ----
    {
        int ar = t >> 2, ks = (t & 3) * 32;  // 4 threads/row, 32 k each
        const float* src = Sr + (size_t)ar * QL + ks;
        uint32_t* dst = A32 + ar * AW + (ks >> 1);
#pragma unroll
        for (int q = 0; q < 8; q++) {
            float4 v = *(const float4*)(src + q * 4);
            dst[q * 2] = pk(v.x, v.y);
            dst[q * 2 + 1] = pk(v.z, v.w);
        }
    }
    // ---- fill Q^T / T^T: read two k-rows, pack pairs, scatter to h rows ----
    {
        int hq = t & 31, kpr = t >> 5;
#pragma unroll
        for (int it = 0; it < 4; it++) {
            int kp = kpr + it * 16;  // 0..63
            int k = kp * 2;
            float4 qa = *(const float4*)(Qb + (size_t)k * HH + h0 + hq * 4);
            float4 qb_ = *(const float4*)(Qb + (size_t)(k + 1) * HH + h0 + hq * 4);
            float4 ta = *(const float4*)(Tb + (size_t)k * HH + h0 + hq * 4);
            float4 tb_ = *(const float4*)(Tb + (size_t)(k + 1) * HH + h0 + hq * 4);
            Q32[(hq * 4 + 0) * AW + kp] = pk(qa.x, qb_.x);
            Q32[(hq * 4 + 1) * AW + kp] = pk(qa.y, qb_.y);
            Q32[(hq * 4 + 2) * AW + kp] = pk(qa.z, qb_.z);
            Q32[(hq * 4 + 3) * AW + kp] = pk(qa.w, qb_.w);
            T32[(hq * 4 + 0) * AW + kp] = pk(ta.x, tb_.x);
            T32[(hq * 4 + 1) * AW + kp] = pk(ta.y, tb_.y);
            T32[(hq * 4 + 2) * AW + kp] = pk(ta.z, tb_.z);
            T32[(hq * 4 + 3) * AW + kp] = pk(ta.w, tb_.w);
        }
    }
    __syncthreads();

    float accA[2][4][4] = {}, accB[2][4][4] = {};
#pragma unroll
    for (int kc = 0; kc < 8; kc++) {  // 8 x (k16 = 8 kp) covers all 64 kp = K=128
        int kb = kc * 8;
        uint32_t af[2][4], bq[4][2], bt[4][2];
#pragma unroll
        for (int mi = 0; mi < 2; mi++) {
            int mb = m0w + mi * 16;
            af[mi][0] = A32[(mb + r) * AW + kb + c];
            af[mi][1] = A32[(mb + r + 8) * AW + kb + c];
            af[mi][2] = A32[(mb + r) * AW + kb + c + 4];
            af[mi][3] = A32[(mb + r + 8) * AW + kb + c + 4];
        }
#pragma unroll
        for (int ni = 0; ni < 4; ni++) {
            int nb = n0w + ni * 8 + r;
            bq[ni][0] = Q32[nb * AW + kb + c];
            bq[ni][1] = Q32[nb * AW + kb + c + 4];
            bt[ni][0] = T32[nb * AW + kb + c];
            bt[ni][1] = T32[nb * AW + kb + c + 4];
        }
#pragma unroll
        for (int mi = 0; mi < 2; mi++)
#pragma unroll
            for (int ni = 0; ni < 4; ni++) {
                mma16(accA[mi][ni], af[mi], bq[ni]);
                mma16(accB[mi][ni], af[mi], bt[ni]);
            }
    }
    const float* Cb = C + (size_t)b * CL * HH;
#pragma unroll
    for (int mi = 0; mi < 2; mi++)
#pragma unroll
        for (int dh = 0; dh < 2; dh++) {
            int i = i0 + m0w + mi * 16 + r + dh * 8;
            const float* Crow = Cb + (size_t)i * HH;
            float* ob = out + ((size_t)b * CL + i) * (4 * HH);
#pragma unroll
            for (int ni = 0; ni < 4; ni++) {
                int h = h0 + n0w + ni * 8 + (c << 1);
                float2 cv = *(const float2*)(Crow + h);
                float2 a2 = make_float2(accA[mi][ni][dh * 2], accA[mi][ni][dh * 2 + 1]);
                float2 b2 = make_float2(accB[mi][ni][dh * 2], accB[mi][ni][dh * 2 + 1]);
                *(float2*)(ob + h) = cv;
                *(float2*)(ob + HH + h) = a2;
                *(float2*)(ob + 2 * HH + h) = make_float2(cv.x * a2.x, cv.y * a2.y);
                *(float2*)(ob + 3 * HH + h) = make_float2(cv.x * b2.x, cv.y * b2.y);
            }
        }
}

// ---------------------------------------------------------------------------
extern "C" void kernel_launch(void* const* d_in, const int* in_sizes, int n_in,
                              void* d_out, int out_size) {
    const float* C = (const float*)d_in[0];
    const float* Q = (const float*)d_in[1];
    const int* cmask = (const int*)d_in[2];
    const int* qmask = (const int*)d_in[3];
    const float* w = (const float*)d_in[4];
    const float* bias = (const float*)d_in[5];
    float* out = (float*)d_out;

    static bool attr_done = false;
    if (!attr_done) {
        cudaFuncSetAttribute(k_out, cudaFuncAttributeMaxDynamicSharedMemorySize, 104448);
        attr_done = true;
    }

    k_sgemm<<<dim3(8, 1, BB), 256>>>(C, Q, w, bias, qmask, cmask);
    k_colcomb<<<BB, 128>>>();
    k_tgemm<<<dim3(1, 4, BB), 256>>>(C, cmask);
    k_out<<<dim3(8, 4, BB), 512, 104448>>>(C, Q, out);
}